// round 4
// baseline (speedup 1.0000x reference)
#include <cuda_runtime.h>
#include <cuda_bf16.h>
#include <cstdint>

#define FRONT 3072
#define EMBED 768
#define TOKENS 16384

// ---------------- device scratch (no dynamic alloc allowed) ----------------
__device__ __nv_bfloat16 g_W1hi[EMBED * FRONT];
__device__ __nv_bfloat16 g_W1lo[EMBED * FRONT];
__device__ __nv_bfloat16 g_W2hi[EMBED * EMBED];
__device__ __nv_bfloat16 g_W2lo[EMBED * EMBED];
__device__ float g_Y[TOKENS * EMBED];

// ---------------- tiling ----------------
constexpr int BM = 128;
constexpr int BN = 128;
constexpr int BK = 32;          // bf16 K columns per stage
constexpr int THREADS = 256;

constexpr int ROWB  = 80;       // padded bytes per smem row (32 bf16 = 64B + 16B pad)
constexpr int MAT   = 128 * ROWB;   // one 128-row matrix = 10240 B
constexpr int STAGE = 4 * MAT;      // Ahi, Alo, Bhi, Blo = 40960 B
constexpr int SMEM_TOTAL = 2 * STAGE;  // 81920 B double-buffered
// offsets within a stage
constexpr int OFF_A_HI = 0;
constexpr int OFF_A_LO = MAT;
constexpr int OFF_B_HI = 2 * MAT;
constexpr int OFF_B_LO = 3 * MAT;

// ---------------- PTX helpers (all plain compute_103-legal) ----------------
__device__ __forceinline__ uint32_t smem_u32(const void* p) {
    uint32_t a;
    asm("{ .reg .u64 t; cvta.to.shared.u64 t, %1; cvt.u32.u64 %0, t; }" : "=r"(a) : "l"(p));
    return a;
}

__device__ __forceinline__ void cp16(uint32_t s, const void* g) {
    asm volatile("cp.async.cg.shared.global [%0], [%1], 16;" :: "r"(s), "l"(g));
}
__device__ __forceinline__ void cp_commit() {
    asm volatile("cp.async.commit_group;");
}
__device__ __forceinline__ void cp_wait0() {
    asm volatile("cp.async.wait_group 0;");
}

__device__ __forceinline__ void ldm4(uint32_t r[4], uint32_t a) {
    asm volatile("ldmatrix.sync.aligned.m8n8.x4.shared.b16 {%0,%1,%2,%3}, [%4];"
                 : "=r"(r[0]), "=r"(r[1]), "=r"(r[2]), "=r"(r[3]) : "r"(a));
}

__device__ __forceinline__ void mma16816(float c[4], const uint32_t a[4],
                                         uint32_t b0, uint32_t b1) {
    asm volatile(
        "mma.sync.aligned.m16n8k16.row.col.f32.bf16.bf16.f32 "
        "{%0,%1,%2,%3}, {%4,%5,%6,%7}, {%8,%9}, {%0,%1,%2,%3};"
        : "+f"(c[0]), "+f"(c[1]), "+f"(c[2]), "+f"(c[3])
        : "r"(a[0]), "r"(a[1]), "r"(a[2]), "r"(a[3]), "r"(b0), "r"(b1));
}

// ---------------- weight split prep: fp32 -> bf16 hi + bf16 lo ----------------
__global__ void convert_weights(const float* __restrict__ W1, const float* __restrict__ W2) {
    int i = blockIdx.x * blockDim.x + threadIdx.x;
    if (i < EMBED * FRONT) {
        float x = W1[i];
        __nv_bfloat16 h = __float2bfloat16(x);
        g_W1hi[i] = h;
        g_W1lo[i] = __float2bfloat16(x - __bfloat162float(h));
    }
    if (i < EMBED * EMBED) {
        float x = W2[i];
        __nv_bfloat16 h = __float2bfloat16(x);
        g_W2hi[i] = h;
        g_W2lo[i] = __float2bfloat16(x - __bfloat162float(h));
    }
}

// ---------------- split-bf16 mma.sync GEMM ----------------
// out[m, n] = act( sum_k A[m,k]*B[n,k] + bias[n] ),  A fp32 (opt. gathered),
// B pre-split bf16 hi/lo K-major [N,K].  Split product: AhBh + AhBl + AlBh.
template <bool DO_GELU, bool GATHER>
__global__ void __launch_bounds__(THREADS, 1)
gemm_mma(const float* __restrict__ Asrc,
         const int* __restrict__ gidx,
         const __nv_bfloat16* __restrict__ Bhi,
         const __nv_bfloat16* __restrict__ Blo,
         const float* __restrict__ bias,
         float* __restrict__ out,
         int K) {
    extern __shared__ char sm[];
    const uint32_t sb = smem_u32(sm);

    const int tid = threadIdx.x;
    const int wid = tid >> 5;
    const int l   = tid & 31;
    const int m0  = blockIdx.y * BM;
    const int n0  = blockIdx.x * BN;
    const int wm0 = (wid >> 2) * 64;   // warp M origin (2 warps over M)
    const int wn0 = (wid & 3) * 32;    // warp N origin (4 warps over N)

    // ---- per-thread A source: 2 threads per row, 16 fp32 each ----
    const int ar = tid >> 1;             // 0..127
    const int ac = (tid & 1) * 16;       // 0 or 16
    const float* aptr =
        Asrc + (size_t)(GATHER ? gidx[m0 + ar] : (m0 + ar)) * (size_t)K + ac;
    const int a_swg = (ar >> 3) & 1;

    // ---- per-thread B source: 2 threads per row, 2x16B chunks each ----
    const int br = tid >> 1;
    const int bj = (tid & 1) * 2;        // chunk pair 0-1 or 2-3
    const __nv_bfloat16* bh = Bhi + (size_t)(n0 + br) * (size_t)K + bj * 8;
    const __nv_bfloat16* bl = Blo + (size_t)(n0 + br) * (size_t)K + bj * 8;
    const int b_swg = (br >> 3) & 1;

    float acc[4][4][4];
#pragma unroll
    for (int i = 0; i < 4; ++i)
#pragma unroll
        for (int j = 0; j < 4; ++j)
#pragma unroll
            for (int k = 0; k < 4; ++k) acc[i][j][k] = 0.0f;

    const int nch = K / BK;

    // ---- load helpers (inlined lambdas) ----
    auto load_B = [&](uint32_t stageb, int c) {
        const char* gh = (const char*)(bh + (size_t)c * BK);
        const char* gl = (const char*)(bl + (size_t)c * BK);
#pragma unroll
        for (int q = 0; q < 2; ++q) {
            uint32_t sw = (uint32_t)br * ROWB + (uint32_t)((bj + q) ^ b_swg) * 16u;
            cp16(stageb + OFF_B_HI + sw, gh + q * 16);
            cp16(stageb + OFF_B_LO + sw, gl + q * 16);
        }
    };
    auto load_A = [&](float4 a4[4], int c) {
        const float4* p = (const float4*)(aptr + (size_t)c * BK);
#pragma unroll
        for (int i = 0; i < 4; ++i) a4[i] = p[i];
    };
    auto store_A = [&](char* stagep, const float4 a4[4]) {
#pragma unroll
        for (int q = 0; q < 2; ++q) {
            float4 v0 = a4[2 * q], v1 = a4[2 * q + 1];
            __nv_bfloat162 h0 = __floats2bfloat162_rn(v0.x, v0.y);
            __nv_bfloat162 h1 = __floats2bfloat162_rn(v0.z, v0.w);
            __nv_bfloat162 h2 = __floats2bfloat162_rn(v1.x, v1.y);
            __nv_bfloat162 h3 = __floats2bfloat162_rn(v1.z, v1.w);
            __nv_bfloat162 l0 = __floats2bfloat162_rn(v0.x - __low2float(h0),
                                                      v0.y - __high2float(h0));
            __nv_bfloat162 l1 = __floats2bfloat162_rn(v0.z - __low2float(h1),
                                                      v0.w - __high2float(h1));
            __nv_bfloat162 l2 = __floats2bfloat162_rn(v1.x - __low2float(h2),
                                                      v1.y - __high2float(h2));
            __nv_bfloat162 l3 = __floats2bfloat162_rn(v1.z - __low2float(h3),
                                                      v1.w - __high2float(h3));
            int chunk = (ac >> 3) + q;   // 0..3
            uint32_t sw = (uint32_t)ar * ROWB + (uint32_t)(chunk ^ a_swg) * 16u;
            uint4 hv, lv;
            hv.x = *(uint32_t*)&h0; hv.y = *(uint32_t*)&h1;
            hv.z = *(uint32_t*)&h2; hv.w = *(uint32_t*)&h3;
            lv.x = *(uint32_t*)&l0; lv.y = *(uint32_t*)&l1;
            lv.z = *(uint32_t*)&l2; lv.w = *(uint32_t*)&l3;
            *(uint4*)(stagep + OFF_A_HI + sw) = hv;
            *(uint4*)(stagep + OFF_A_LO + sw) = lv;
        }
    };

    // ldmatrix lane addressing pieces
    const int r15  = l & 15;
    const int half = l >> 4;

    auto compute = [&](uint32_t stageb) {
#pragma unroll
        for (int s = 0; s < 2; ++s) {
            uint32_t Ah[4][4], Al[4][4], Bh[2][4], Bl[2][4];
#pragma unroll
            for (int i = 0; i < 4; ++i) {
                int r = wm0 + i * 16 + r15;
                int chunk = (s * 2 + half) ^ ((r >> 3) & 1);
                uint32_t ad = stageb + (uint32_t)r * ROWB + (uint32_t)chunk * 16u;
                ldm4(Ah[i], ad + OFF_A_HI);
                ldm4(Al[i], ad + OFF_A_LO);
            }
#pragma unroll
            for (int p = 0; p < 2; ++p) {
                int r = wn0 + p * 16 + r15;
                int chunk = (s * 2 + half) ^ ((r >> 3) & 1);
                uint32_t bd = stageb + (uint32_t)r * ROWB + (uint32_t)chunk * 16u;
                ldm4(Bh[p], bd + OFF_B_HI);
                ldm4(Bl[p], bd + OFF_B_LO);
            }
#pragma unroll
            for (int i = 0; i < 4; ++i)
#pragma unroll
                for (int j = 0; j < 4; ++j) {
                    int p = j >> 1, t = j & 1;
                    mma16816(acc[i][j], Ah[i], Bh[p][t], Bh[p][t + 2]);
                    mma16816(acc[i][j], Ah[i], Bl[p][t], Bl[p][t + 2]);
                    mma16816(acc[i][j], Al[i], Bh[p][t], Bh[p][t + 2]);
                }
        }
    };

    // ---- prologue: stage 0 <- chunk 0 ----
    {
        load_B(sb, 0);
        cp_commit();
        float4 a4[4];
        load_A(a4, 0);
        store_A(sm, a4);
        cp_wait0();
        __syncthreads();
    }

    // ---- main loop, double buffered ----
    int cur = 0;
    for (int c = 0; c < nch; ++c) {
        uint32_t sc = sb + (uint32_t)cur * STAGE;
        char*    sn = sm + (cur ^ 1) * STAGE;
        uint32_t snb = sb + (uint32_t)(cur ^ 1) * STAGE;

        float4 a4[4];
        if (c + 1 < nch) {
            load_B(snb, c + 1);
            cp_commit();
            load_A(a4, c + 1);
        }

        compute(sc);

        if (c + 1 < nch) {
            store_A(sn, a4);
            cp_wait0();
            __syncthreads();
        }
        cur ^= 1;
    }

    // ---- epilogue: bias + (exact GELU) + store fp32 ----
    const int er = l >> 2;
    const int ec = (l & 3) * 2;
#pragma unroll
    for (int i = 0; i < 4; ++i)
#pragma unroll
        for (int j = 0; j < 4; ++j) {
            int n = n0 + wn0 + j * 8 + ec;
            float bb0 = bias[n], bb1 = bias[n + 1];
#pragma unroll
            for (int h = 0; h < 2; ++h) {
                int m = m0 + wm0 + i * 16 + er + h * 8;
                float v0 = acc[i][j][2 * h]     + bb0;
                float v1 = acc[i][j][2 * h + 1] + bb1;
                if (DO_GELU) {
                    v0 = 0.5f * v0 * (1.0f + erff(v0 * 0.70710678118654752f));
                    v1 = 0.5f * v1 * (1.0f + erff(v1 * 0.70710678118654752f));
                }
                float2 o; o.x = v0; o.y = v1;
                *(float2*)(out + (size_t)m * EMBED + n) = o;
            }
        }
}

// ---------------- harness entry ----------------
extern "C" void kernel_launch(void* const* d_in, const int* in_sizes, int n_in,
                              void* d_out, int out_size) {
    const int*   idxs = (const int*)d_in[0];
    const float* tok  = (const float*)d_in[1];
    const float* W1   = (const float*)d_in[2];
    const float* b1   = (const float*)d_in[3];
    const float* W2   = (const float*)d_in[4];
    const float* b2   = (const float*)d_in[5];
    float* out = (float*)d_out;

    void *w1h, *w1l, *w2h, *w2l, *y;
    cudaGetSymbolAddress(&w1h, g_W1hi);
    cudaGetSymbolAddress(&w1l, g_W1lo);
    cudaGetSymbolAddress(&w2h, g_W2hi);
    cudaGetSymbolAddress(&w2l, g_W2lo);
    cudaGetSymbolAddress(&y,   g_Y);

    cudaFuncSetAttribute(gemm_mma<true, true>,
                         cudaFuncAttributeMaxDynamicSharedMemorySize, SMEM_TOTAL);
    cudaFuncSetAttribute(gemm_mma<false, false>,
                         cudaFuncAttributeMaxDynamicSharedMemorySize, SMEM_TOTAL);

    const int nW = EMBED * FRONT;
    convert_weights<<<(nW + 255) / 256, 256>>>(W1, W2);

    // GEMM1: gathered embed @ W1^T + b1, exact GELU -> Y (fp32 scratch)
    gemm_mma<true, true><<<dim3(EMBED / BN, TOKENS / BM), THREADS, SMEM_TOTAL>>>(
        tok, idxs, (const __nv_bfloat16*)w1h, (const __nv_bfloat16*)w1l, b1,
        (float*)y, FRONT);

    // GEMM2: Y @ W2^T + b2 -> out
    gemm_mma<false, false><<<dim3(EMBED / BN, TOKENS / BM), THREADS, SMEM_TOTAL>>>(
        (const float*)y, nullptr, (const __nv_bfloat16*)w2h, (const __nv_bfloat16*)w2l, b2,
        out, EMBED);
}